// round 6
// baseline (speedup 1.0000x reference)
#include <cuda_runtime.h>
#include <cstdint>

// DynamicTimeStretch: out[t] = (alpha*n[idx+1] + (1-alpha)*n[idx])^2,
// n[j] = |spec[j]|. Phase accumulation cancels under abs()^2.
// Persistent blocks, cp.async-pipelined: copy(row k+1) overlaps consume(row k).

#define N_ROWS (16 * 513)     // 8208
#define T_IN 2048
#define N_OUT 2276
#define N_OUT4 (N_OUT / 4)    // 569
#define RATE 0.9f
#define THREADS 288
#define GRID (148 * 7)        // 1036 blocks, ~8 rows each

__device__ __forceinline__ void cp_async16(uint32_t saddr, const void* gptr) {
    asm volatile("cp.async.cg.shared.global [%0], [%1], 16;\n"
                 :: "r"(saddr), "l"(gptr) : "memory");
}
__device__ __forceinline__ void cp_commit() {
    asm volatile("cp.async.commit_group;\n" ::: "memory");
}
__device__ __forceinline__ void cp_wait_all() {
    asm volatile("cp.async.wait_group 0;\n" ::: "memory");
}

__global__ void __launch_bounds__(THREADS, 7)
dts_kernel(const float* __restrict__ xr,
           const float* __restrict__ xi,
           float* __restrict__ out)
{
    __shared__ float4 raw[1024];        // [0:512) = r row, [512:1024) = i row
    __shared__ float  n[T_IN + 4];      // norms + sentinel n[2048]=0

    const int tid = threadIdx.x;
    uint32_t raw_addr;
    asm("{ .reg .u64 t; cvta.to.shared.u64 t, %1; cvt.u32.u64 %0, t; }"
        : "=r"(raw_addr) : "l"((const void*)raw));

    if (tid == 0) n[T_IN] = 0.0f;       // persists across rows

    int row = blockIdx.x;

    // Prologue: issue async copy of first row
    {
        const float4* r4 = (const float4*)(xr + (long)row * T_IN);
        const float4* i4 = (const float4*)(xi + (long)row * T_IN);
        #pragma unroll
        for (int v = 0; v < 4; v++) {
            const int j = tid + v * THREADS;       // [0,1152)
            if (j < 512)        cp_async16(raw_addr + j * 16, r4 + j);
            else if (j < 1024)  cp_async16(raw_addr + j * 16, i4 + (j - 512));
        }
        cp_commit();
    }

    for (; row < N_ROWS; row += GRID) {
        cp_wait_all();          // raw holds this row
        __syncthreads();

        // Norms: raw -> n (512 float4 items over 288 threads, 2 iters)
        #pragma unroll
        for (int v = 0; v < 2; v++) {
            const int j = tid + v * THREADS;
            if (j < 512) {
                const float4 rr = raw[j];
                const float4 ii = raw[512 + j];
                float4 s;
                s.x = sqrtf(fmaf(rr.x, rr.x, ii.x * ii.x));
                s.y = sqrtf(fmaf(rr.y, rr.y, ii.y * ii.y));
                s.z = sqrtf(fmaf(rr.z, rr.z, ii.z * ii.z));
                s.w = sqrtf(fmaf(rr.w, rr.w, ii.w * ii.w));
                ((float4*)n)[j] = s;
            }
        }
        __syncthreads();        // raw fully read; n fully written

        // Issue next row's copy NOW — overlaps with consume below
        const int nrow = row + GRID;
        if (nrow < N_ROWS) {
            const float4* r4 = (const float4*)(xr + (long)nrow * T_IN);
            const float4* i4 = (const float4*)(xi + (long)nrow * T_IN);
            #pragma unroll
            for (int v = 0; v < 4; v++) {
                const int j = tid + v * THREADS;
                if (j < 512)        cp_async16(raw_addr + j * 16, r4 + j);
                else if (j < 1024)  cp_async16(raw_addr + j * 16, i4 + (j - 512));
            }
        }
        cp_commit();            // empty group when no next row — legal

        // Consume: 569 float4 outputs over 288 threads (2 iters, 98.8% eff)
        float* orow = out + (long)row * N_OUT;
        #pragma unroll
        for (int v = 0; v < 2; v++) {
            const int o4 = tid + v * THREADS;
            if (o4 < N_OUT4) {
                float4 res;
                #pragma unroll
                for (int k = 0; k < 4; k++) {
                    const int t = o4 * 4 + k;
                    // Match jax f32 arithmetic exactly
                    const float ts = (float)t * RATE;
                    const int idx = (int)ts;
                    const float a = ts - (float)idx;
                    const float m = fmaf(a, n[idx + 1], (1.0f - a) * n[idx]);
                    ((float*)&res)[k] = m * m;
                }
                __stcs((float4*)orow + o4, res);
            }
        }
        // No barrier needed here: next iteration's wait+syncthreads orders
        // consume(row) before norms overwrite n.
    }
}

extern "C" void kernel_launch(void* const* d_in, const int* in_sizes, int n_in,
                              void* d_out, int out_size)
{
    const float* xr = (const float*)d_in[0];
    const float* xi = (const float*)d_in[1];
    float* out = (float*)d_out;

    dts_kernel<<<GRID, THREADS>>>(xr, xi, out);
}